// round 6
// baseline (speedup 1.0000x reference)
#include <cuda_runtime.h>
#include <cuda_bf16.h>
#include <cstdint>

// DifferentiableTopKSelector == per-row hard top-32 mask of raw scores
// (straight-through estimator is value-identical to hard_mask; `u` is dead).
//
// Round 5: full TMA data path. The L1tex wavefront pipe was the ceiling
// (~65-70%) when both the 128 MB read and the 128 MB write streamed through
// LDG/STG. Now: TMA bulk-load row -> smem, detect candidates via LDS,
// exact stable rank on ~88 composite keys, build the 0/1 mask in smem in
// place, TMA bulk-store smem -> out. Zero LDG/STG on the bulk path.

static constexpr int COLS = 8192;
static constexpr int NT   = 256;
static constexpr int VPT  = COLS / 4 / NT;   // 8 float4 per thread
static constexpr int CAP  = 256;
static constexpr int KSEL = 32;
static constexpr unsigned ROW_BYTES = COLS * 4;   // 32 KB
#define GUESS 2.3f

__device__ __forceinline__ uint32_t smem_u32(const void* p) {
    uint32_t a;
    asm("{ .reg .u64 t; cvta.to.shared.u64 t, %1; cvt.u32.u64 %0, t; }"
        : "=r"(a) : "l"(p));
    return a;
}

__device__ __forceinline__ unsigned long long pack_key(float v, unsigned idx) {
    // v > GUESS > 0: float bits compare as unsigned. Inverted index makes
    // larger composite == (larger value, then smaller index) — exactly
    // jax.lax.top_k's stable tie-break.
    return ((unsigned long long)__float_as_uint(v) << 32)
         | (unsigned long long)(COLS - 1u - idx);
}

__global__ void __launch_bounds__(NT)
topk_mask_kernel(const float* __restrict__ scores, float* __restrict__ out) {
    __shared__ __align__(128) float buf[COLS];          // 32 KB row / mask
    __shared__ unsigned long long  cand[CAP];           // 2 KB
    __shared__ unsigned            w[KSEL];             // winner indices
    __shared__ int                 s_cnt;
    __shared__ __align__(8) unsigned long long mbar;

    const int t = threadIdx.x;
    const size_t rowoff = (size_t)blockIdx.x * (size_t)COLS;

    if (t == 0) {
        s_cnt = 0;
        asm volatile("mbarrier.init.shared.b64 [%0], 1;"
                     :: "r"(smem_u32(&mbar)) : "memory");
    }
    __syncthreads();

    const uint32_t mb      = smem_u32(&mbar);
    const uint32_t bufaddr = smem_u32(buf);

    // ---- TMA bulk load: full 32 KB row, one instruction ----
    if (t == 0) {
        asm volatile("mbarrier.arrive.expect_tx.shared.b64 _, [%0], %1;"
                     :: "r"(mb), "r"(ROW_BYTES) : "memory");
        asm volatile(
            "cp.async.bulk.shared::cta.global.mbarrier::complete_tx::bytes "
            "[%0], [%1], %2, [%3];"
            :: "r"(bufaddr), "l"(scores + rowoff), "r"(ROW_BYTES), "r"(mb)
            : "memory");
    }
    // wait (parity 0), acquire so the LDS reads below are ordered
    asm volatile(
        "{\n\t.reg .pred P;\n"
        "W%=:\n\t"
        "mbarrier.try_wait.parity.acquire.cta.shared::cta.b64 P, [%0], 0, 0x989680;\n\t"
        "@!P bra W%=;\n\t}"
        :: "r"(mb) : "memory");

    // ---- candidate detection from smem (conflict-free LDS.128) ----
    const float4* b4 = (const float4*)buf;
    #pragma unroll
    for (int it = 0; it < VPT; ++it) {
        float4 v = b4[t + it * NT];
        if (fmaxf(fmaxf(v.x, v.y), fmaxf(v.z, v.w)) > GUESS) {
            unsigned long long loc[4];
            int n = 0;
            const unsigned base = (unsigned)((t + it * NT) * 4);
            if (v.x > GUESS) loc[n++] = pack_key(v.x, base + 0u);
            if (v.y > GUESS) loc[n++] = pack_key(v.y, base + 1u);
            if (v.z > GUESS) loc[n++] = pack_key(v.z, base + 2u);
            if (v.w > GUESS) loc[n++] = pack_key(v.w, base + 3u);
            int slot = atomicAdd(&s_cnt, n);
            for (int q = 0; q < n; ++q)
                if (slot + q < CAP) cand[slot + q] = loc[q];
        }
    }
    __syncthreads();

    const int cnt = s_cnt;

    if (cnt >= KSEL && cnt <= CAP) {
        // ---- exact stable rank; ranks unique -> direct slot write ----
        if (t < cnt) {
            const unsigned long long ci = cand[t];
            int r = 0;
            #pragma unroll 4
            for (int j = 0; j < cnt; ++j)
                r += (cand[j] > ci);                 // LDS.64 broadcast
            if (r < KSEL)
                w[r] = COLS - 1u - (unsigned)(ci & 0xFFFFFFFFull);
        }
    } else if (t == 0) {
        // ---- exact serial fallback over the smem copy (guard only) ----
        float    bk[KSEL];
        unsigned bi[KSEL];
        #pragma unroll
        for (int i = 0; i < KSEL; ++i) { bk[i] = -INFINITY; bi[i] = 0u; }
        for (int i = 0; i < COLS; ++i) {
            float vv = buf[i];
            if (vv > bk[KSEL - 1]) {                 // strict > == stable
                int p = KSEL - 1;
                while (p > 0 && vv > bk[p - 1]) {
                    bk[p] = bk[p - 1]; bi[p] = bi[p - 1]; --p;
                }
                bk[p] = vv; bi[p] = (unsigned)i;
            }
        }
        for (int i = 0; i < KSEL; ++i) w[i] = bi[i];
    }
    __syncthreads();

    // ---- build mask in place: zero the row, set the 32 winners ----
    float4* bw = (float4*)buf;
    const float4 z = make_float4(0.f, 0.f, 0.f, 0.f);
    #pragma unroll
    for (int it = 0; it < VPT; ++it)
        bw[t + it * NT] = z;
    __syncthreads();
    if (t < KSEL)
        buf[w[t]] = 1.0f;
    __syncthreads();

    // ---- TMA bulk store: smem -> gmem, bypasses L1 ----
    asm volatile("fence.proxy.async.shared::cta;" ::: "memory");
    if (t == 0) {
        asm volatile(
            "cp.async.bulk.global.shared::cta.bulk_group [%0], [%1], %2;"
            :: "l"(out + rowoff), "r"(bufaddr), "r"(ROW_BYTES) : "memory");
        asm volatile("cp.async.bulk.commit_group;" ::: "memory");
        asm volatile("cp.async.bulk.wait_group 0;" ::: "memory");
    }
}

extern "C" void kernel_launch(void* const* d_in, const int* in_sizes, int n_in,
                              void* d_out, int out_size) {
    const float* scores = (const float*)d_in[0];   // (4096, 8192) fp32
    // d_in[1] (u) is mathematically dead: output == hard top-k mask of scores.
    float* out = (float*)d_out;
    const int rows = out_size / COLS;              // 4096
    topk_mask_kernel<<<rows, NT>>>(scores, out);
}